// round 14
// baseline (speedup 1.0000x reference)
#include <cuda_runtime.h>

#define B_TOTAL 131072
#define NFEAT   64
#define NNUM    48
#define NCAT    16
#define NCLS    32
#define H0      40
#define H1      20
#define TBL     1024
#define NCELL   4096
#define KCLAMP  1.0e4f
#define XSYNTH  -16.0f

// device-global tables (allocation-free)
__device__ float          g_x[NNUM][TBL];     // knot x, padded +huge
__device__ float2         g_ys[NNUM][TBL];    // (y, slope-to-next)
__device__ unsigned short g_bk[NNUM][NCELL];  // bucket -> knot index

// ---------------------------------------------------------------------------
// Setup: exact PWL table per numeric feature (1024 threads, bitonic sort).
// Net is exactly PWL in scalar x: knots = layer0 zeros U h1 zero-crossings.
// ---------------------------------------------------------------------------
__global__ __launch_bounds__(1024)
void gam_setup_kernel(const float* __restrict__ W0, const float* __restrict__ b0,
                      const float* __restrict__ W1, const float* __restrict__ b1,
                      const float* __restrict__ W2, const float* __restrict__ b2)
{
    const int f   = blockIdx.x;
    const int tid = threadIdx.x;

    __shared__ float sa[H0], sc[H0], sk[H0];
    __shared__ float sH[H0 + 2][H1];
    __shared__ float list[TBL];
    __shared__ float sx[TBL];
    __shared__ float sW1[H0 * H1], sb1[H1], sW2[H1];
    __shared__ float syr, sb2v;
    __shared__ int   cnt;

    if (tid == 0) cnt = 0;
    if (tid < H0) { sa[tid] = W0[f * H0 + tid]; sc[tid] = b0[f * H0 + tid]; }
    for (int i = tid; i < H0 * H1; i += 1024) sW1[i] = W1[f * H0 * H1 + i];
    if (tid < H1) { sb1[tid] = b1[f * H1 + tid]; sW2[tid] = W2[f * H1 + tid]; }
    if (tid == 0) sb2v = b2[f];
    __syncthreads();

    // layer0 knots (clamped), stable rank-sort into sk (tiny: 40x40)
    if (tid < H0) {
        float a = sa[tid], c = sc[tid];
        float kx = (a != 0.0f) ? fminf(fmaxf(-c / a, -KCLAMP), KCLAMP) : KCLAMP;
        int r = 0;
        for (int j = 0; j < H0; j++) {
            float aj = sa[j], cj = sc[j];
            float kj = (aj != 0.0f) ? fminf(fmaxf(-cj / aj, -KCLAMP), KCLAMP) : KCLAMP;
            if (kj < kx || (kj == kx && j < tid)) r++;
        }
        sk[r] = kx;
    }
    __syncthreads();

    // h1[p] exactly at each sorted base knot + probes at sk0-1, sk39+1
    for (int idx = tid; idx < (H0 + 2) * H1; idx += 1024) {
        int k = idx / H1, p = idx % H1;
        float x = (k < H0) ? sk[k] : (k == H0 ? sk[0] - 1.0f : sk[H0 - 1] + 1.0f);
        float acc = sb1[p];
        for (int o = 0; o < H0; o++)
            acc += sW1[o * H1 + p] * fmaxf(sa[o] * x + sc[o], 0.0f);
        sH[k][p] = acc;
    }
    if (tid < H0) list[atomicAdd(&cnt, 1)] = sk[tid];
    if (tid == 0) list[atomicAdd(&cnt, 1)] = XSYNTH;   // synthetic left anchor
    __syncthreads();

    // interior zero-crossings of h1[p]
    for (int idx = tid; idx < (H0 - 1) * H1; idx += 1024) {
        int k = idx / H1, p = idx % H1;
        float y0 = sH[k][p], y1 = sH[k + 1][p];
        if ((y0 > 0.0f) != (y1 > 0.0f)) {
            float xs = sk[k] - y0 * (sk[k + 1] - sk[k]) / (y1 - y0);
            xs = fminf(fmaxf(xs, -KCLAMP), KCLAMP);
            list[atomicAdd(&cnt, 1)] = xs;
        }
    }
    // tail crossings (finite-difference slopes from probes)
    if (tid < H1) {
        int p = tid;
        float y0 = sH[0][p];
        float sl = sH[0][p] - sH[H0][p];
        if (sl != 0.0f && y0 != 0.0f && (y0 / sl) > 0.0f) {
            float xs = fminf(fmaxf(sk[0] - y0 / sl, -KCLAMP), KCLAMP);
            list[atomicAdd(&cnt, 1)] = xs;
        }
        float y1 = sH[H0 - 1][p];
        float sr = sH[H0 + 1][p] - sH[H0 - 1][p];
        if (sr != 0.0f && y1 != 0.0f && (y1 / sr) < 0.0f) {
            float xs = fminf(fmaxf(sk[H0 - 1] - y1 / sr, -KCLAMP), KCLAMP);
            list[atomicAdd(&cnt, 1)] = xs;
        }
    }
    __syncthreads();
    const int n = cnt;   // <= 862

    // copy + pad, then bitonic sort sx[0..1024) ascending (equal keys
    // interchangeable: duplicate x values produce identical exact y)
    sx[tid] = (tid < n) ? list[tid] : 3.4e38f;
    __syncthreads();
    #pragma unroll
    for (int k = 2; k <= TBL; k <<= 1) {
        #pragma unroll
        for (int j = k >> 1; j > 0; j >>= 1) {
            int ixj = tid ^ j;
            if (ixj > tid) {
                float a = sx[tid], b = sx[ixj];
                bool descend = (tid & k) != 0;
                if ((a > b) != descend) { sx[tid] = b; sx[ixj] = a; }
            }
            __syncthreads();
        }
    }

    // exact full-network evals at every knot + right probe
    for (int idx = tid; idx < n + 1; idx += 1024) {
        float x = (idx == n) ? sx[n - 1] + 1.0f : sx[idx];
        float h1v[H1];
        #pragma unroll
        for (int p = 0; p < H1; p++) h1v[p] = sb1[p];
        for (int o = 0; o < H0; o++) {
            float h0 = fmaxf(sa[o] * x + sc[o], 0.0f);
            #pragma unroll
            for (int p = 0; p < H1; p++) h1v[p] += sW1[o * H1 + p] * h0;
        }
        float yv = sb2v;
        #pragma unroll
        for (int p = 0; p < H1; p++) yv += sW2[p] * fmaxf(h1v[p], 0.0f);
        if (idx == n) syr = yv; else list[idx] = yv;
    }
    __syncthreads();

    // emit table (x, y, slope)
    for (int k = tid; k < TBL; k += 1024) {
        float xk = sx[k];
        float yk = (k < n) ? list[k] : 0.0f;
        float s = 0.0f;
        if (k < n - 1) {
            float dx = sx[k + 1] - xk;
            if (dx > 0.0f) s = (list[k + 1] - yk) / dx;
        } else if (k == n - 1) {
            s = syr - yk;                  // right tail (dx = 1)
        }
        g_x[f][k]  = xk;
        g_ys[f][k] = make_float2(yk, s);
    }
    // bucket LUT: cell c over [-8,8] -> last knot with x <= cell_left
    for (int c = tid; c < NCELL; c += 1024) {
        float cl = -8.0f + (float)c * (16.0f / NCELL);
        int k = 0;
        #pragma unroll
        for (int b = 512; b >= 1; b >>= 1) {
            int t = k + b;
            if (t < TBL && sx[t] <= cl) k = t;
        }
        g_bk[f][c] = (unsigned short)k;
    }
}

// ---------------------------------------------------------------------------
// Fused eval: block group g owns features [g*8, g*8+8) — a 32B span of every
// row. Threads read/write row-major directly (full 32B sectors, no transpose).
// Lane pairs split the two float4 halves so adjacent lanes share cache lines.
// Groups 0..5 = numeric (8 PWL tables in smem, 160KB); 6..7 = categorical.
// ---------------------------------------------------------------------------
#define FG      8
#define EVROWS  4096                       // (1024/2 threads) * 8 rows
#define EV_SMEM (FG * (4096 + 8192 + 8192))   // 163840 B

__device__ __forceinline__ float lut_eval(float xv, const float* tx,
                                          const float2* tys,
                                          const unsigned short* sb)
{
    int cell = __float2int_rz(fmaf(xv, (float)NCELL / 16.0f, (float)NCELL / 2));
    cell = max(0, min(NCELL - 1, cell));
    int k = sb[cell];
    while (tx[k + 1] <= xv) k++;
    while (k > 0 && tx[k] > xv) k--;          // guard: x below bucket grid
    float2 ys = tys[k];
    return fmaf(xv - tx[k], ys.y, ys.x);
}

__global__ __launch_bounds__(1024)
void gam_eval_kernel(const float* __restrict__ inputs,
                     const float* __restrict__ class_bias,
                     float* __restrict__ out)
{
    extern __shared__ __align__(16) unsigned char esm[];
    const int g   = blockIdx.y;
    const int tid = threadIdx.x;
    const int h   = tid & 1;                          // which float4 of the 32B span
    const int rb  = blockIdx.x * EVROWS + (tid >> 1) * 8;   // 8 rows per thread
    const int c4  = g * 2 + h;                        // float4 index within row

    const float4* src = (const float4*)inputs;
    float4*       dst = (float4*)out;

    if (g < 6) {
        float*          stx  = (float*)esm;                        // FG x 1024
        float2*         stys = (float2*)(esm + FG * 4096);         // FG x 1024
        unsigned short* sbk  = (unsigned short*)(esm + FG * 4096 + FG * 8192);
        const int f0 = g * FG;

        for (int i = tid; i < FG * 256; i += 1024) {               // tx: 32KB
            int j = i >> 8, w = i & 255;
            ((float4*)(stx + j * 1024))[w] = ((const float4*)g_x[f0 + j])[w];
        }
        for (int i = tid; i < FG * 512; i += 1024) {               // tys: 64KB
            int j = i >> 9, w = i & 511;
            ((float4*)(stys + j * 1024))[w] = ((const float4*)g_ys[f0 + j])[w];
        }
        for (int i = tid; i < FG * 512; i += 1024) {               // bk: 64KB
            int j = i >> 9, w = i & 511;
            ((uint4*)(sbk + j * 4096))[w] = ((const uint4*)g_bk[f0 + j])[w];
        }
        __syncthreads();

        const int jb = h * 4;                 // this lane's 4 features in group
        const float*          t0 = stx  + (jb + 0) * 1024;
        const float*          t1 = stx  + (jb + 1) * 1024;
        const float*          t2 = stx  + (jb + 2) * 1024;
        const float*          t3 = stx  + (jb + 3) * 1024;
        const float2*         y0 = stys + (jb + 0) * 1024;
        const float2*         y1 = stys + (jb + 1) * 1024;
        const float2*         y2 = stys + (jb + 2) * 1024;
        const float2*         y3 = stys + (jb + 3) * 1024;
        const unsigned short* b0 = sbk  + (jb + 0) * 4096;
        const unsigned short* b1 = sbk  + (jb + 1) * 4096;
        const unsigned short* b2 = sbk  + (jb + 2) * 4096;
        const unsigned short* b3 = sbk  + (jb + 3) * 4096;

        float4 xv[8];
        #pragma unroll
        for (int i = 0; i < 8; i++)           // 8 independent 16B loads (MLP=8)
            xv[i] = src[(size_t)(rb + i) * 16 + c4];

        #pragma unroll
        for (int i = 0; i < 8; i++) {
            float4 y;
            y.x = lut_eval(xv[i].x, t0, y0, b0);
            y.y = lut_eval(xv[i].y, t1, y1, b1);
            y.z = lut_eval(xv[i].z, t2, y2, b2);
            y.w = lut_eval(xv[i].w, t3, y3, b3);
            dst[(size_t)(rb + i) * 16 + c4] = y;
        }
    } else {
        float* scb = (float*)esm;             // 16 x 32 class_bias
        if (tid < 128) ((float4*)scb)[tid] = ((const float4*)class_bias)[tid];
        __syncthreads();

        const int cb = (g - 6) * 8 + h * 4;   // cat feature base (0..15)
        float4 xv[8];
        #pragma unroll
        for (int i = 0; i < 8; i++)
            xv[i] = src[(size_t)(rb + i) * 16 + c4];   // c4 = 12..15 here

        #pragma unroll
        for (int i = 0; i < 8; i++) {
            float4 y;
            y.x = scb[(cb + 0) * NCLS + (int)xv[i].x];
            y.y = scb[(cb + 1) * NCLS + (int)xv[i].y];
            y.z = scb[(cb + 2) * NCLS + (int)xv[i].z];
            y.w = scb[(cb + 3) * NCLS + (int)xv[i].w];
            dst[(size_t)(rb + i) * 16 + c4] = y;
        }
    }
}

extern "C" void kernel_launch(void* const* d_in, const int* in_sizes, int n_in,
                              void* d_out, int out_size)
{
    const float* inputs     = (const float*)d_in[0];
    const float* W0         = (const float*)d_in[1];
    const float* b0         = (const float*)d_in[2];
    const float* W1         = (const float*)d_in[3];
    const float* b1         = (const float*)d_in[4];
    const float* W2         = (const float*)d_in[5];
    const float* b2         = (const float*)d_in[6];
    const float* class_bias = (const float*)d_in[7];
    float* out = (float*)d_out;

    cudaFuncSetAttribute(gam_eval_kernel,
                         cudaFuncAttributeMaxDynamicSharedMemorySize, EV_SMEM);

    gam_setup_kernel<<<NNUM, 1024>>>(W0, b0, W1, b1, W2, b2);

    dim3 ge(B_TOTAL / EVROWS, 8);             // 32 x 8 (6 numeric + 2 cat groups)
    gam_eval_kernel<<<ge, 1024, EV_SMEM>>>(inputs, class_bias, out);
}